// round 4
// baseline (speedup 1.0000x reference)
#include <cuda_runtime.h>

#define SCALING 0.17677669529663687f

// ---------------------------------------------------------------------------
// Scratch (static device globals — allowed; no runtime allocation)
// ---------------------------------------------------------------------------
__device__ float g_proj[9][32][1024][32];   // 37.7 MB  head-major projections
__device__ float g_mask[32][1024 * 1024];   // 134 MB   local_mask per bh
__device__ float g_attn_pre[4096 * 256];    // 4 MB     attn before out-proj

// ---------------------------------------------------------------------------
// packed f32x2 helpers (sm_103a FFMA2 path)
// ---------------------------------------------------------------------------
typedef unsigned long long u64t;

__device__ __forceinline__ u64t pack2(float lo, float hi) {
    u64t r;
    asm("mov.b64 %0, {%1, %2};" : "=l"(r) : "f"(lo), "f"(hi));
    return r;
}
__device__ __forceinline__ void unpack2(u64t v, float& lo, float& hi) {
    asm("mov.b64 {%0, %1}, %2;" : "=f"(lo), "=f"(hi) : "l"(v));
}
__device__ __forceinline__ u64t fma2(u64t a, u64t b, u64t c) {
    u64t d;
    asm("fma.rn.f32x2 %0, %1, %2, %3;" : "=l"(d) : "l"(a), "l"(b), "l"(c));
    return d;
}

// ---------------------------------------------------------------------------
// warp helpers
// ---------------------------------------------------------------------------
__device__ __forceinline__ float warp_iscan(float v, int lane) {
    #pragma unroll
    for (int o = 1; o < 32; o <<= 1) {
        float u = __shfl_up_sync(0xffffffffu, v, o);
        if (lane >= o) v += u;
    }
    return v;
}
// softmax over a 1024-long row in SMEM, one warp
__device__ __forceinline__ void warp_softmax_row(float* row, int lane) {
    float m = -1e30f;
    #pragma unroll
    for (int q = 0; q < 32; q++) m = fmaxf(m, row[q * 32 + lane]);
    #pragma unroll
    for (int o = 16; o; o >>= 1) m = fmaxf(m, __shfl_xor_sync(0xffffffffu, m, o));
    float ssum = 0.f;
    #pragma unroll
    for (int q = 0; q < 32; q++) {
        float e = __expf(row[q * 32 + lane] - m);
        row[q * 32 + lane] = e;
        ssum += e;
    }
    #pragma unroll
    for (int o = 16; o; o >>= 1) ssum += __shfl_xor_sync(0xffffffffu, ssum, o);
    float inv = 1.0f / ssum;
    #pragma unroll
    for (int q = 0; q < 32; q++) row[q * 32 + lane] *= inv;
}

// ---------------------------------------------------------------------------
// Kernel 1: packed in-projection.  C[4096 x 2304] = X_sel @ W^T + b  (scaled)
// scattered into g_proj[j][bh][s][d].  FFMA2 inner product.
// ---------------------------------------------------------------------------
__global__ void __launch_bounds__(256) proj_kernel(
        const float* __restrict__ xq, const float* __restrict__ xk,
        const float* __restrict__ xv, const float* __restrict__ W,
        const float* __restrict__ bias)
{
    __shared__ float As[16][68];
    __shared__ float Bs[16][68];
    int ct = blockIdx.x;                 // 36 column tiles of 64
    int rt = blockIdx.y;                 // 64 row tiles of 64
    int j = ct >> 2;                     // projection slice (4 tiles per slice)
    const float* X = (j == 2) ? xv
                   : ((j == 1 || j == 4 || j == 6 || j == 8) ? xk : xq);
    int t = threadIdx.x;
    int tx = t & 15, ty = t >> 4;
    int row0 = rt * 64, col0 = ct * 64;
    u64t acc2[4][2] = {};
    for (int kt = 0; kt < 256; kt += 16) {
        #pragma unroll
        for (int l = 0; l < 4; l++) {
            int u = t + l * 256;
            int kk = u & 15, m = u >> 4;
            As[kk][m] = X[(row0 + m) * 256 + kt + kk];
            Bs[kk][m] = W[(col0 + m) * 256 + kt + kk];
        }
        __syncthreads();
        #pragma unroll
        for (int kk = 0; kk < 16; kk++) {
            float4 av = *(const float4*)(&As[kk][ty * 4]);
            ulonglong2 bv = *(const ulonglong2*)(&Bs[kk][tx * 4]);
            u64t a0 = pack2(av.x, av.x), a1 = pack2(av.y, av.y);
            u64t a2 = pack2(av.z, av.z), a3 = pack2(av.w, av.w);
            acc2[0][0] = fma2(a0, bv.x, acc2[0][0]);
            acc2[0][1] = fma2(a0, bv.y, acc2[0][1]);
            acc2[1][0] = fma2(a1, bv.x, acc2[1][0]);
            acc2[1][1] = fma2(a1, bv.y, acc2[1][1]);
            acc2[2][0] = fma2(a2, bv.x, acc2[2][0]);
            acc2[2][1] = fma2(a2, bv.y, acc2[2][1]);
            acc2[3][0] = fma2(a3, bv.x, acc2[3][0]);
            acc2[3][1] = fma2(a3, bv.y, acc2[3][1]);
        }
        __syncthreads();
    }
    float scale = (j == 0 || j == 7) ? SCALING : 1.0f;
    #pragma unroll
    for (int i = 0; i < 4; i++) {
        int row = row0 + ty * 4 + i;
        int s = row >> 2, b = row & 3;
        #pragma unroll
        for (int cp = 0; cp < 2; cp++) {
            float lo, hi;
            unpack2(acc2[i][cp], lo, hi);
            int col = col0 + tx * 4 + cp * 2;
            int eo0 = col - j * 256, eo1 = eo0 + 1;
            g_proj[j][b * 8 + (eo0 >> 5)][s][eo0 & 31] = (lo + bias[col]) * scale;
            g_proj[j][b * 8 + (eo1 >> 5)][s][eo1 & 31] = (hi + bias[col + 1]) * scale;
        }
    }
}

// ---------------------------------------------------------------------------
// K tile stage: 256 cols x 32 d into KT[col*33 + d]
// ---------------------------------------------------------------------------
#define STAGE_K_TILE(Ksrc, ct)                                               \
    for (int u = threadIdx.x * 4; u < 8192; u += 1024) {                     \
        int col = u >> 5, dd = u & 31;                                       \
        float4 kv = *(const float4*)((Ksrc) + ((ct) * 256 + col) * 32 + dd); \
        KT[col * 33 + dd + 0] = kv.x;                                        \
        KT[col * 33 + dd + 1] = kv.y;                                        \
        KT[col * 33 + dd + 2] = kv.z;                                        \
        KT[col * 33 + dd + 3] = kv.w;                                        \
    }

// 16-row x 1-col logit micro-tile, FFMA2: acc2[p] packs rows (2p, 2p+1)
__device__ __forceinline__ void logit_mac2(const float* __restrict__ KT,
                                           const float* __restrict__ Qt,
                                           int t, u64t acc2[8])
{
    const float* kp = KT + t * 33;
    #pragma unroll
    for (int d = 0; d < 32; d++) {
        float kv = kp[d];
        u64t kvv = pack2(kv, kv);
        const ulonglong2* qp = (const ulonglong2*)(Qt + d * 16);
        ulonglong2 qa = qp[0], qb = qp[1], qc = qp[2], qd = qp[3];
        acc2[0] = fma2(qa.x, kvv, acc2[0]);
        acc2[1] = fma2(qa.y, kvv, acc2[1]);
        acc2[2] = fma2(qb.x, kvv, acc2[2]);
        acc2[3] = fma2(qb.y, kvv, acc2[3]);
        acc2[4] = fma2(qc.x, kvv, acc2[4]);
        acc2[5] = fma2(qc.y, kvv, acc2[5]);
        acc2[6] = fma2(qd.x, kvv, acc2[6]);
        acc2[7] = fma2(qd.y, kvv, acc2[7]);
    }
}

// ---------------------------------------------------------------------------
// FUSED kernel: per (bh, 16 rows):
//   A) left/right logits  B) softmax  C) scans -> mask (smem + gmem)
//   D) global/local logits + combine  E) softmax  F) AV
// dyn smem: Ls[16*1024] Rs[16*1024] KT[256*33] Qt[512] = 166912 B
// ---------------------------------------------------------------------------
__global__ void __launch_bounds__(256) fused_kernel()
{
    extern __shared__ float sm[];
    float* Ls = sm;                 // floats: 16384
    float* Rs = sm + 16384;         // 16384
    float* KT = sm + 32768;         // 8448
    float* Qt = sm + 41216;         // 512
    int t = threadIdx.x, lane = t & 31, w = t >> 5;
    int rt = blockIdx.x, bh = blockIdx.y;
    int row0 = rt * 16;

    // ---- Phase A: left/right logits --------------------------------------
    for (int m = 0; m < 2; m++) {
        const float* Qsrc = &g_proj[m == 0 ? 3 : 5][bh][0][0];
        const float* Ksrc = &g_proj[m == 0 ? 4 : 6][bh][0][0];
        float* Obuf = (m == 0) ? Ls : Rs;
        __syncthreads();
        for (int u = t; u < 512; u += 256) {
            int i = u >> 5, d = u & 31;
            Qt[d * 16 + i] = Qsrc[(row0 + i) * 32 + d];
        }
        for (int ct = 0; ct < 4; ct++) {
            __syncthreads();
            STAGE_K_TILE(Ksrc, ct)
            __syncthreads();
            u64t acc2[8] = {};
            logit_mac2(KT, Qt, t, acc2);
            #pragma unroll
            for (int p = 0; p < 8; p++) {
                float lo, hi;
                unpack2(acc2[p], lo, hi);
                Obuf[(2 * p) * 1024 + ct * 256 + t] = lo;
                Obuf[(2 * p + 1) * 1024 + ct * 256 + t] = hi;
            }
        }
    }
    __syncthreads();

    // ---- Phase B: softmax (warp w owns rows w, w+8) -----------------------
    warp_softmax_row(Ls + w * 1024, lane);
    warp_softmax_row(Ls + (w + 8) * 1024, lane);
    warp_softmax_row(Rs + w * 1024, lane);
    warp_softmax_row(Rs + (w + 8) * 1024, lane);

    // ---- Phase C: 2-level prefix/suffix -> mask ---------------------------
    // P2[q][r] = sum_{q'<=q} p[q'][r]   (per-LANE prefix accumulated!)
    // S2[q][r] = sum_{q'>=q} s[q'][r],  s = B - p + v  (within-block suffix)
    for (int rr = 0; rr < 2; rr++) {
        int r = w + rr * 8;
        float* Lrow = Ls + r * 1024;
        float* Rrow = Rs + r * 1024;
        float sL[32], sR[32];
        {
            float runP = 0.f;
            #pragma unroll
            for (int q = 0; q < 32; q++) {
                float v = Lrow[q * 32 + lane];
                float p = warp_iscan(v, lane);
                float B = __shfl_sync(0xffffffffu, p, 31);
                runP += p;                        // per-lane accumulation
                Lrow[q * 32 + lane] = runP;       // P2(L)
                sL[q] = B - p + v;
            }
        }
        {
            float runP = 0.f;
            #pragma unroll
            for (int q = 0; q < 32; q++) {
                float v = Rrow[q * 32 + lane];
                float p = warp_iscan(v, lane);
                float B = __shfl_sync(0xffffffffu, p, 31);
                runP += p;                        // per-lane accumulation
                Rrow[q * 32 + lane] = runP;       // P2(R)
                sR[q] = B - p + v;
            }
        }
        float* mout = &g_mask[bh][(size_t)(row0 + r) * 1024];
        float runSL = 0.f, runSR = 0.f;
        #pragma unroll
        for (int q = 31; q >= 0; q--) {
            runSL += sL[q];                       // S2(L)[q]
            runSR += sR[q];                       // S2(R)[q]
            float mv = Lrow[q * 32 + lane] * runSR
                     + runSL * Rrow[q * 32 + lane];
            Lrow[q * 32 + lane] = mv;             // mask kept in Ls
            mout[q * 32 + lane] = mv;             // and to gmem for reduce
        }
    }
    __syncthreads();

    // ---- Phase D: global/local logits + combine (Cs = Rs reused) ---------
    float* Cs = Rs;
    for (int m = 0; m < 2; m++) {
        const float* Qsrc = &g_proj[m == 0 ? 0 : 7][bh][0][0];
        const float* Ksrc = &g_proj[m == 0 ? 1 : 8][bh][0][0];
        __syncthreads();
        for (int u = t; u < 512; u += 256) {
            int i = u >> 5, d = u & 31;
            Qt[d * 16 + i] = Qsrc[(row0 + i) * 32 + d];
        }
        for (int ct = 0; ct < 4; ct++) {
            __syncthreads();
            STAGE_K_TILE(Ksrc, ct)
            __syncthreads();
            u64t acc2[8] = {};
            logit_mac2(KT, Qt, t, acc2);
            if (m == 0) {
                #pragma unroll
                for (int p = 0; p < 8; p++) {
                    float lo, hi;
                    unpack2(acc2[p], lo, hi);
                    Cs[(2 * p) * 1024 + ct * 256 + t] = lo;
                    Cs[(2 * p + 1) * 1024 + ct * 256 + t] = hi;
                }
            } else {
                #pragma unroll
                for (int p = 0; p < 8; p++) {
                    float lo, hi;
                    unpack2(acc2[p], lo, hi);
                    int i0 = 2 * p, i1 = 2 * p + 1;
                    int c = ct * 256 + t;
                    Cs[i0 * 1024 + c] = 0.1f * Cs[i0 * 1024 + c] + lo * Ls[i0 * 1024 + c];
                    Cs[i1 * 1024 + c] = 0.1f * Cs[i1 * 1024 + c] + hi * Ls[i1 * 1024 + c];
                }
            }
        }
    }
    __syncthreads();

    // ---- Phase E: softmax attn weights ------------------------------------
    warp_softmax_row(Cs + w * 1024, lane);
    warp_softmax_row(Cs + (w + 8) * 1024, lane);

    // ---- Phase F: AV (FFMA2 along j; accumulator packs adjacent j) --------
    int d = t & 31, ip = t >> 5;
    int i0 = ip, i1 = ip + 8;
    u64t a0 = 0, a1 = 0;
    const float* Vsrc = &g_proj[2][bh][0][0];
    for (int jt = 0; jt < 4; jt++) {
        __syncthreads();
        STAGE_K_TILE(Vsrc, jt)          // reuse KT as V tile
        __syncthreads();
        const float* vp = KT + d;
        #pragma unroll
        for (int j = 0; j < 256; j += 4) {
            ulonglong2 c0 = *(const ulonglong2*)(Cs + i0 * 1024 + jt * 256 + j);
            ulonglong2 c1 = *(const ulonglong2*)(Cs + i1 * 1024 + jt * 256 + j);
            u64t v01 = pack2(vp[(j + 0) * 33], vp[(j + 1) * 33]);
            u64t v23 = pack2(vp[(j + 2) * 33], vp[(j + 3) * 33]);
            a0 = fma2(c0.x, v01, a0);
            a0 = fma2(c0.y, v23, a0);
            a1 = fma2(c1.x, v01, a1);
            a1 = fma2(c1.y, v23, a1);
        }
    }
    float a0lo, a0hi, a1lo, a1hi;
    unpack2(a0, a0lo, a0hi);
    unpack2(a1, a1lo, a1hi);
    int b = bh >> 3, h = bh & 7;
    g_attn_pre[((row0 + i0) * 4 + b) * 256 + h * 32 + d] = a0lo + a0hi;
    g_attn_pre[((row0 + i1) * 4 + b) * 256 + h * 32 + d] = a1lo + a1hi;
}

// ---------------------------------------------------------------------------
// Kernel 4: out-projection.  out[4096 x 256] = attn_pre @ out_w^T + out_b
// ---------------------------------------------------------------------------
__global__ void __launch_bounds__(256) outproj_kernel(
        const float* __restrict__ W, const float* __restrict__ bias,
        float* __restrict__ out)
{
    __shared__ float As[16][68];
    __shared__ float Bs[16][68];
    int ct = blockIdx.x;  // 4
    int rt = blockIdx.y;  // 64
    int t = threadIdx.x;
    int tx = t & 15, ty = t >> 4;
    int row0 = rt * 64, col0 = ct * 64;
    u64t acc2[4][2] = {};
    for (int kt = 0; kt < 256; kt += 16) {
        #pragma unroll
        for (int l = 0; l < 4; l++) {
            int u = t + l * 256;
            int kk = u & 15, m = u >> 4;
            As[kk][m] = g_attn_pre[(row0 + m) * 256 + kt + kk];
            Bs[kk][m] = W[(col0 + m) * 256 + kt + kk];
        }
        __syncthreads();
        #pragma unroll
        for (int kk = 0; kk < 16; kk++) {
            float4 av = *(const float4*)(&As[kk][ty * 4]);
            ulonglong2 bv = *(const ulonglong2*)(&Bs[kk][tx * 4]);
            u64t a0 = pack2(av.x, av.x), a1 = pack2(av.y, av.y);
            u64t a2 = pack2(av.z, av.z), a3 = pack2(av.w, av.w);
            acc2[0][0] = fma2(a0, bv.x, acc2[0][0]);
            acc2[0][1] = fma2(a0, bv.y, acc2[0][1]);
            acc2[1][0] = fma2(a1, bv.x, acc2[1][0]);
            acc2[1][1] = fma2(a1, bv.y, acc2[1][1]);
            acc2[2][0] = fma2(a2, bv.x, acc2[2][0]);
            acc2[2][1] = fma2(a2, bv.y, acc2[2][1]);
            acc2[3][0] = fma2(a3, bv.x, acc2[3][0]);
            acc2[3][1] = fma2(a3, bv.y, acc2[3][1]);
        }
        __syncthreads();
    }
    #pragma unroll
    for (int i = 0; i < 4; i++) {
        int row = row0 + ty * 4 + i;
        #pragma unroll
        for (int cp = 0; cp < 2; cp++) {
            float lo, hi;
            unpack2(acc2[i][cp], lo, hi);
            int col = col0 + tx * 4 + cp * 2;
            out[row * 256 + col] = lo + bias[col];
            out[row * 256 + col + 1] = hi + bias[col + 1];
        }
    }
}

// ---------------------------------------------------------------------------
// Kernel 5: consistent_mask = sum over bh of g_mask
// ---------------------------------------------------------------------------
__global__ void __launch_bounds__(256) mask_reduce_kernel(float* __restrict__ out)
{
    int idx = blockIdx.x * 256 + threadIdx.x;
    float s = 0.f;
    #pragma unroll
    for (int bh = 0; bh < 32; bh++) s += g_mask[bh][idx];
    out[idx] = s;
}

// ---------------------------------------------------------------------------
extern "C" void kernel_launch(void* const* d_in, const int* in_sizes, int n_in,
                              void* d_out, int out_size)
{
    const float* q   = (const float*)d_in[0];
    const float* k   = (const float*)d_in[1];
    const float* v   = (const float*)d_in[2];
    const float* ipw = (const float*)d_in[3];
    const float* ipb = (const float*)d_in[4];
    const float* ow  = (const float*)d_in[5];
    const float* ob  = (const float*)d_in[6];
    float* out = (float*)d_out;

    cudaFuncSetAttribute(fused_kernel, cudaFuncAttributeMaxDynamicSharedMemorySize, 166912);

    proj_kernel<<<dim3(36, 64), 256>>>(q, k, v, ipw, ipb);
    fused_kernel<<<dim3(64, 32), 256, 166912>>>();
    outproj_kernel<<<dim3(4, 64), 256>>>(ow, ob, out);
    mask_reduce_kernel<<<4096, 256>>>(out + 1048576);
}

// round 5
// speedup vs baseline: 1.0087x; 1.0087x over previous
#include <cuda_runtime.h>

#define SCALING 0.17677669529663687f

// ---------------------------------------------------------------------------
// Scratch (static device globals — allowed; no runtime allocation)
// ---------------------------------------------------------------------------
__device__ float g_proj[9][32][1024][32];   // 37.7 MB  head-major projections
__device__ float g_mask[32][1024 * 1024];   // 134 MB   local_mask per bh
__device__ float g_attn_pre[4096 * 256];    // 4 MB     attn before out-proj

// ---------------------------------------------------------------------------
// warp helpers
// ---------------------------------------------------------------------------
// two interleaved inclusive scans (independent SHFL chains -> 2x ILP)
__device__ __forceinline__ void warp_iscan2(float& a, float& b, int lane) {
    #pragma unroll
    for (int o = 1; o < 32; o <<= 1) {
        float ua = __shfl_up_sync(0xffffffffu, a, o);
        float ub = __shfl_up_sync(0xffffffffu, b, o);
        if (lane >= o) { a += ua; b += ub; }
    }
}
// softmax over two 1024-long rows in SMEM, interleaved (MUFU/SHFL overlap)
__device__ __forceinline__ void warp_softmax_row2(float* r0, float* r1, int lane) {
    float m0 = -1e30f, m1 = -1e30f;
    #pragma unroll
    for (int q = 0; q < 32; q++) {
        m0 = fmaxf(m0, r0[q * 32 + lane]);
        m1 = fmaxf(m1, r1[q * 32 + lane]);
    }
    #pragma unroll
    for (int o = 16; o; o >>= 1) {
        m0 = fmaxf(m0, __shfl_xor_sync(0xffffffffu, m0, o));
        m1 = fmaxf(m1, __shfl_xor_sync(0xffffffffu, m1, o));
    }
    float s0 = 0.f, s1 = 0.f;
    #pragma unroll
    for (int q = 0; q < 32; q++) {
        float e0 = __expf(r0[q * 32 + lane] - m0);
        float e1 = __expf(r1[q * 32 + lane] - m1);
        r0[q * 32 + lane] = e0;
        r1[q * 32 + lane] = e1;
        s0 += e0; s1 += e1;
    }
    #pragma unroll
    for (int o = 16; o; o >>= 1) {
        s0 += __shfl_xor_sync(0xffffffffu, s0, o);
        s1 += __shfl_xor_sync(0xffffffffu, s1, o);
    }
    float i0 = 1.0f / s0, i1 = 1.0f / s1;
    #pragma unroll
    for (int q = 0; q < 32; q++) {
        r0[q * 32 + lane] *= i0;
        r1[q * 32 + lane] *= i1;
    }
}

// ---------------------------------------------------------------------------
// Kernel 1: packed in-projection.  C[4096 x 2304] = X_sel @ W^T + b  (scaled)
// scattered into g_proj[j][bh][s][d].  Scalar FFMA (R2-proven).
// ---------------------------------------------------------------------------
__global__ void __launch_bounds__(256) proj_kernel(
        const float* __restrict__ xq, const float* __restrict__ xk,
        const float* __restrict__ xv, const float* __restrict__ W,
        const float* __restrict__ bias)
{
    __shared__ float As[16][68];
    __shared__ float Bs[16][68];
    int ct = blockIdx.x;                 // 36 column tiles of 64
    int rt = blockIdx.y;                 // 64 row tiles of 64
    int j = ct >> 2;                     // projection slice (4 tiles per slice)
    const float* X = (j == 2) ? xv
                   : ((j == 1 || j == 4 || j == 6 || j == 8) ? xk : xq);
    int t = threadIdx.x;
    int tx = t & 15, ty = t >> 4;
    int row0 = rt * 64, col0 = ct * 64;
    float acc[4][4] = {};
    for (int kt = 0; kt < 256; kt += 16) {
        #pragma unroll
        for (int l = 0; l < 4; l++) {
            int u = t + l * 256;
            int kk = u & 15, m = u >> 4;
            As[kk][m] = X[(row0 + m) * 256 + kt + kk];
            Bs[kk][m] = W[(col0 + m) * 256 + kt + kk];
        }
        __syncthreads();
        #pragma unroll
        for (int kk = 0; kk < 16; kk++) {
            float4 av = *(const float4*)(&As[kk][ty * 4]);
            float4 bv = *(const float4*)(&Bs[kk][tx * 4]);
            float a[4] = {av.x, av.y, av.z, av.w};
            float b[4] = {bv.x, bv.y, bv.z, bv.w};
            #pragma unroll
            for (int i = 0; i < 4; i++)
                #pragma unroll
                for (int c = 0; c < 4; c++)
                    acc[i][c] += a[i] * b[c];
        }
        __syncthreads();
    }
    float scale = (j == 0 || j == 7) ? SCALING : 1.0f;
    #pragma unroll
    for (int i = 0; i < 4; i++) {
        int row = row0 + ty * 4 + i;
        int s = row >> 2, b = row & 3;
        #pragma unroll
        for (int c = 0; c < 4; c++) {
            int col = col0 + tx * 4 + c;
            int eo = col - j * 256;
            float val = (acc[i][c] + bias[col]) * scale;
            g_proj[j][b * 8 + (eo >> 5)][s][eo & 31] = val;
        }
    }
}

// ---------------------------------------------------------------------------
// K tile stage into a given KT buffer: 256 cols x 32 d -> KT[col*33 + d]
// ---------------------------------------------------------------------------
__device__ __forceinline__ void stage_tile(float* __restrict__ KT,
                                           const float* __restrict__ Ksrc,
                                           int ct, int t)
{
    for (int u = t * 4; u < 8192; u += 1024) {
        int col = u >> 5, dd = u & 31;
        float4 kv = *(const float4*)(Ksrc + (size_t)(ct * 256 + col) * 32 + dd);
        KT[col * 33 + dd + 0] = kv.x;
        KT[col * 33 + dd + 1] = kv.y;
        KT[col * 33 + dd + 2] = kv.z;
        KT[col * 33 + dd + 3] = kv.w;
    }
}

// 16-row x 1-col logit micro-tile, scalar FFMA (R2-proven)
__device__ __forceinline__ void logit_mac(const float* __restrict__ KT,
                                          const float* __restrict__ Qt,
                                          int t, float acc[16])
{
    const float* kp = KT + t * 33;
    #pragma unroll
    for (int d = 0; d < 32; d++) {
        float kv = kp[d];
        const float4* qp = (const float4*)(Qt + d * 16);
        float4 q0 = qp[0], q1 = qp[1], q2 = qp[2], q3 = qp[3];
        acc[0]  += q0.x * kv; acc[1]  += q0.y * kv;
        acc[2]  += q0.z * kv; acc[3]  += q0.w * kv;
        acc[4]  += q1.x * kv; acc[5]  += q1.y * kv;
        acc[6]  += q1.z * kv; acc[7]  += q1.w * kv;
        acc[8]  += q2.x * kv; acc[9]  += q2.y * kv;
        acc[10] += q2.z * kv; acc[11] += q2.w * kv;
        acc[12] += q3.x * kv; acc[13] += q3.y * kv;
        acc[14] += q3.z * kv; acc[15] += q3.w * kv;
    }
}

// ---------------------------------------------------------------------------
// FUSED kernel: per (bh, 16 rows):
//   A) left/right logits  B) softmax  C) scans -> mask (smem + gmem)
//   D) global/local logits + combine  E) softmax  F) AV
// dyn smem floats: Ls[16384] Rs[16384] KT0[8448] KT1[8448] Qt[512] = 200704 B
// Double-buffered tile staging: 1 sync/tile, LDG overlapped with FFMA.
// ---------------------------------------------------------------------------
__global__ void __launch_bounds__(256) fused_kernel()
{
    extern __shared__ float sm[];
    float* Ls  = sm;                 // 16384
    float* Rs  = sm + 16384;         // 16384
    float* KT0 = sm + 32768;         // 8448
    float* KT1 = sm + 41216;         // 8448
    float* Qt  = sm + 49664;         // 512
    int t = threadIdx.x, lane = t & 31, w = t >> 5;
    int rt = blockIdx.x, bh = blockIdx.y;
    int row0 = rt * 16;

    // ---- Phase A: left/right logits ---------------------------------------
    #pragma unroll 1
    for (int m = 0; m < 2; m++) {
        const float* Qsrc = &g_proj[m == 0 ? 3 : 5][bh][0][0];
        const float* Ksrc = &g_proj[m == 0 ? 4 : 6][bh][0][0];
        float* Obuf = (m == 0) ? Ls : Rs;
        __syncthreads();                       // Qt/KT reuse guard
        for (int u = t; u < 512; u += 256) {
            int i = u >> 5, d = u & 31;
            Qt[d * 16 + i] = Qsrc[(row0 + i) * 32 + d];
        }
        stage_tile(KT0, Ksrc, 0, t);
        __syncthreads();
        #pragma unroll 1
        for (int ct = 0; ct < 4; ct++) {
            float* cur = (ct & 1) ? KT1 : KT0;
            float* nxt = (ct & 1) ? KT0 : KT1;
            if (ct < 3) stage_tile(nxt, Ksrc, ct + 1, t);
            float acc[16];
            #pragma unroll
            for (int i = 0; i < 16; i++) acc[i] = 0.f;
            logit_mac(cur, Qt, t, acc);
            #pragma unroll
            for (int i = 0; i < 16; i++) Obuf[i * 1024 + ct * 256 + t] = acc[i];
            __syncthreads();
        }
    }

    // ---- Phase B: softmax (warp w owns rows w, w+8 of both) ----------------
    warp_softmax_row2(Ls + w * 1024, Ls + (w + 8) * 1024, lane);
    warp_softmax_row2(Rs + w * 1024, Rs + (w + 8) * 1024, lane);

    // ---- Phase C: 2-level prefix/suffix -> mask ----------------------------
    // P2[q][lane] = sum_{q'<=q} p[q'][lane];  S2 via s = B - p + v reversed.
    for (int rr = 0; rr < 2; rr++) {
        int r = w + rr * 8;
        float* Lrow = Ls + r * 1024;
        float* Rrow = Rs + r * 1024;
        float sL[32], sR[32];
        float runPL = 0.f, runPR = 0.f;
        #pragma unroll
        for (int q = 0; q < 32; q++) {
            float vL = Lrow[q * 32 + lane];
            float vR = Rrow[q * 32 + lane];
            float pL = vL, pR = vR;
            warp_iscan2(pL, pR, lane);
            float BL = __shfl_sync(0xffffffffu, pL, 31);
            float BR = __shfl_sync(0xffffffffu, pR, 31);
            runPL += pL;                      // per-lane accumulation
            runPR += pR;
            Lrow[q * 32 + lane] = runPL;      // P2(L)
            Rrow[q * 32 + lane] = runPR;      // P2(R)
            sL[q] = BL - pL + vL;
            sR[q] = BR - pR + vR;
        }
        float* mout = &g_mask[bh][(size_t)(row0 + r) * 1024];
        float runSL = 0.f, runSR = 0.f;
        #pragma unroll
        for (int q = 31; q >= 0; q--) {
            runSL += sL[q];                   // S2(L)[q]
            runSR += sR[q];                   // S2(R)[q]
            float mv = Lrow[q * 32 + lane] * runSR
                     + runSL * Rrow[q * 32 + lane];
            Lrow[q * 32 + lane] = mv;         // mask kept in Ls
            mout[q * 32 + lane] = mv;         // and to gmem for reduce
        }
    }
    __syncthreads();

    // ---- Phase D: global/local logits + combine (Cs = Rs reused) ----------
    float* Cs = Rs;
    #pragma unroll 1
    for (int m = 0; m < 2; m++) {
        const float* Qsrc = &g_proj[m == 0 ? 0 : 7][bh][0][0];
        const float* Ksrc = &g_proj[m == 0 ? 1 : 8][bh][0][0];
        __syncthreads();
        for (int u = t; u < 512; u += 256) {
            int i = u >> 5, d = u & 31;
            Qt[d * 16 + i] = Qsrc[(row0 + i) * 32 + d];
        }
        stage_tile(KT0, Ksrc, 0, t);
        __syncthreads();
        #pragma unroll 1
        for (int ct = 0; ct < 4; ct++) {
            float* cur = (ct & 1) ? KT1 : KT0;
            float* nxt = (ct & 1) ? KT0 : KT1;
            if (ct < 3) stage_tile(nxt, Ksrc, ct + 1, t);
            float acc[16];
            #pragma unroll
            for (int i = 0; i < 16; i++) acc[i] = 0.f;
            logit_mac(cur, Qt, t, acc);
            if (m == 0) {
                #pragma unroll
                for (int i = 0; i < 16; i++) Cs[i * 1024 + ct * 256 + t] = acc[i];
            } else {
                #pragma unroll
                for (int i = 0; i < 16; i++) {
                    int idx = i * 1024 + ct * 256 + t;
                    Cs[idx] = 0.1f * Cs[idx] + acc[i] * Ls[idx];
                }
            }
            __syncthreads();
        }
    }

    // ---- Phase E: softmax attn weights -------------------------------------
    warp_softmax_row2(Cs + w * 1024, Cs + (w + 8) * 1024, lane);
    __syncthreads();

    // ---- Phase F: AV (scalar FFMA, double-buffered V tiles) ---------------
    int d = t & 31, ip = t >> 5;
    int i0 = ip, i1 = ip + 8;
    float a0 = 0.f, a1 = 0.f;
    const float* Vsrc = &g_proj[2][bh][0][0];
    stage_tile(KT0, Vsrc, 0, t);
    __syncthreads();
    #pragma unroll 1
    for (int jt = 0; jt < 4; jt++) {
        float* cur = (jt & 1) ? KT1 : KT0;
        float* nxt = (jt & 1) ? KT0 : KT1;
        if (jt < 3) stage_tile(nxt, Vsrc, jt + 1, t);
        const float* vp = cur + d;
        #pragma unroll
        for (int j = 0; j < 256; j += 4) {
            float4 c0 = *(const float4*)(Cs + i0 * 1024 + jt * 256 + j);
            float4 c1 = *(const float4*)(Cs + i1 * 1024 + jt * 256 + j);
            float v0 = vp[(j + 0) * 33], v1 = vp[(j + 1) * 33];
            float v2 = vp[(j + 2) * 33], v3 = vp[(j + 3) * 33];
            a0 += c0.x * v0 + c0.y * v1 + c0.z * v2 + c0.w * v3;
            a1 += c1.x * v0 + c1.y * v1 + c1.z * v2 + c1.w * v3;
        }
        __syncthreads();
    }
    int b = bh >> 3, h = bh & 7;
    g_attn_pre[((row0 + i0) * 4 + b) * 256 + h * 32 + d] = a0;
    g_attn_pre[((row0 + i1) * 4 + b) * 256 + h * 32 + d] = a1;
}

// ---------------------------------------------------------------------------
// Kernel 4: out-projection.  out[4096 x 256] = attn_pre @ out_w^T + out_b
// ---------------------------------------------------------------------------
__global__ void __launch_bounds__(256) outproj_kernel(
        const float* __restrict__ W, const float* __restrict__ bias,
        float* __restrict__ out)
{
    __shared__ float As[16][68];
    __shared__ float Bs[16][68];
    int ct = blockIdx.x;  // 4
    int rt = blockIdx.y;  // 64
    int t = threadIdx.x;
    int tx = t & 15, ty = t >> 4;
    int row0 = rt * 64, col0 = ct * 64;
    float acc[4][4] = {};
    for (int kt = 0; kt < 256; kt += 16) {
        #pragma unroll
        for (int l = 0; l < 4; l++) {
            int u = t + l * 256;
            int kk = u & 15, m = u >> 4;
            As[kk][m] = g_attn_pre[(row0 + m) * 256 + kt + kk];
            Bs[kk][m] = W[(col0 + m) * 256 + kt + kk];
        }
        __syncthreads();
        #pragma unroll
        for (int kk = 0; kk < 16; kk++) {
            float4 av = *(const float4*)(&As[kk][ty * 4]);
            float4 bv = *(const float4*)(&Bs[kk][tx * 4]);
            float a[4] = {av.x, av.y, av.z, av.w};
            float b[4] = {bv.x, bv.y, bv.z, bv.w};
            #pragma unroll
            for (int i = 0; i < 4; i++)
                #pragma unroll
                for (int c = 0; c < 4; c++)
                    acc[i][c] += a[i] * b[c];
        }
        __syncthreads();
    }
    #pragma unroll
    for (int i = 0; i < 4; i++) {
        int row = row0 + ty * 4 + i;
        #pragma unroll
        for (int c = 0; c < 4; c++) {
            int col = col0 + tx * 4 + c;
            out[row * 256 + col] = acc[i][c] + bias[col];
        }
    }
}

// ---------------------------------------------------------------------------
// Kernel 5: consistent_mask = sum over bh of g_mask
// ---------------------------------------------------------------------------
__global__ void __launch_bounds__(256) mask_reduce_kernel(float* __restrict__ out)
{
    int idx = blockIdx.x * 256 + threadIdx.x;
    float s = 0.f;
    #pragma unroll
    for (int bh = 0; bh < 32; bh++) s += g_mask[bh][idx];
    out[idx] = s;
}

// ---------------------------------------------------------------------------
extern "C" void kernel_launch(void* const* d_in, const int* in_sizes, int n_in,
                              void* d_out, int out_size)
{
    const float* q   = (const float*)d_in[0];
    const float* k   = (const float*)d_in[1];
    const float* v   = (const float*)d_in[2];
    const float* ipw = (const float*)d_in[3];
    const float* ipb = (const float*)d_in[4];
    const float* ow  = (const float*)d_in[5];
    const float* ob  = (const float*)d_in[6];
    float* out = (float*)d_out;

    cudaFuncSetAttribute(fused_kernel, cudaFuncAttributeMaxDynamicSharedMemorySize, 200704);

    proj_kernel<<<dim3(36, 64), 256>>>(q, k, v, ipw, ipb);
    fused_kernel<<<dim3(64, 32), 256, 200704>>>();
    outproj_kernel<<<dim3(4, 64), 256>>>(ow, ob, out);
    mask_reduce_kernel<<<4096, 256>>>(out + 1048576);
}

// round 6
// speedup vs baseline: 1.2240x; 1.2135x over previous
#include <cuda_runtime.h>

#define SCALING 0.17677669529663687f

// ---------------------------------------------------------------------------
// Scratch (static device globals — allowed; no runtime allocation)
// ---------------------------------------------------------------------------
__device__ float g_proj[9][32][1024][32];   // 37.7 MB  head-major projections
__device__ float g_mask[32][1024 * 1024];   // 134 MB   local_mask per bh
__device__ float g_attn_pre[4096 * 256];    // 4 MB     attn before out-proj

// ---------------------------------------------------------------------------
// warp helpers
// ---------------------------------------------------------------------------
// two interleaved inclusive scans (independent SHFL chains -> 2x ILP)
__device__ __forceinline__ void warp_iscan2(float& a, float& b, int lane) {
    #pragma unroll
    for (int o = 1; o < 32; o <<= 1) {
        float ua = __shfl_up_sync(0xffffffffu, a, o);
        float ub = __shfl_up_sync(0xffffffffu, b, o);
        if (lane >= o) { a += ua; b += ub; }
    }
}
// softmax over one 1024-long row in SMEM
__device__ __forceinline__ void warp_softmax_row(float* row, int lane) {
    float m = -1e30f;
    #pragma unroll
    for (int q = 0; q < 32; q++) m = fmaxf(m, row[q * 32 + lane]);
    #pragma unroll
    for (int o = 16; o; o >>= 1) m = fmaxf(m, __shfl_xor_sync(0xffffffffu, m, o));
    float s = 0.f;
    #pragma unroll
    for (int q = 0; q < 32; q++) {
        float e = __expf(row[q * 32 + lane] - m);
        row[q * 32 + lane] = e;
        s += e;
    }
    #pragma unroll
    for (int o = 16; o; o >>= 1) s += __shfl_xor_sync(0xffffffffu, s, o);
    float inv = 1.0f / s;
    #pragma unroll
    for (int q = 0; q < 32; q++) row[q * 32 + lane] *= inv;
}
// softmax over two rows interleaved (MUFU/SHFL overlap)
__device__ __forceinline__ void warp_softmax_row2(float* r0, float* r1, int lane) {
    float m0 = -1e30f, m1 = -1e30f;
    #pragma unroll
    for (int q = 0; q < 32; q++) {
        m0 = fmaxf(m0, r0[q * 32 + lane]);
        m1 = fmaxf(m1, r1[q * 32 + lane]);
    }
    #pragma unroll
    for (int o = 16; o; o >>= 1) {
        m0 = fmaxf(m0, __shfl_xor_sync(0xffffffffu, m0, o));
        m1 = fmaxf(m1, __shfl_xor_sync(0xffffffffu, m1, o));
    }
    float s0 = 0.f, s1 = 0.f;
    #pragma unroll
    for (int q = 0; q < 32; q++) {
        float e0 = __expf(r0[q * 32 + lane] - m0);
        float e1 = __expf(r1[q * 32 + lane] - m1);
        r0[q * 32 + lane] = e0;
        r1[q * 32 + lane] = e1;
        s0 += e0; s1 += e1;
    }
    #pragma unroll
    for (int o = 16; o; o >>= 1) {
        s0 += __shfl_xor_sync(0xffffffffu, s0, o);
        s1 += __shfl_xor_sync(0xffffffffu, s1, o);
    }
    float i0 = 1.0f / s0, i1 = 1.0f / s1;
    #pragma unroll
    for (int q = 0; q < 32; q++) {
        r0[q * 32 + lane] *= i0;
        r1[q * 32 + lane] *= i1;
    }
}

// ---------------------------------------------------------------------------
// Kernel 1: packed in-projection (scalar FFMA, R2-proven)
// ---------------------------------------------------------------------------
__global__ void __launch_bounds__(256) proj_kernel(
        const float* __restrict__ xq, const float* __restrict__ xk,
        const float* __restrict__ xv, const float* __restrict__ W,
        const float* __restrict__ bias)
{
    __shared__ float As[16][68];
    __shared__ float Bs[16][68];
    int ct = blockIdx.x;                 // 36 column tiles of 64
    int rt = blockIdx.y;                 // 64 row tiles of 64
    int j = ct >> 2;
    const float* X = (j == 2) ? xv
                   : ((j == 1 || j == 4 || j == 6 || j == 8) ? xk : xq);
    int t = threadIdx.x;
    int tx = t & 15, ty = t >> 4;
    int row0 = rt * 64, col0 = ct * 64;
    float acc[4][4] = {};
    for (int kt = 0; kt < 256; kt += 16) {
        #pragma unroll
        for (int l = 0; l < 4; l++) {
            int u = t + l * 256;
            int kk = u & 15, m = u >> 4;
            As[kk][m] = X[(row0 + m) * 256 + kt + kk];
            Bs[kk][m] = W[(col0 + m) * 256 + kt + kk];
        }
        __syncthreads();
        #pragma unroll
        for (int kk = 0; kk < 16; kk++) {
            float4 av = *(const float4*)(&As[kk][ty * 4]);
            float4 bv = *(const float4*)(&Bs[kk][tx * 4]);
            float a[4] = {av.x, av.y, av.z, av.w};
            float b[4] = {bv.x, bv.y, bv.z, bv.w};
            #pragma unroll
            for (int i = 0; i < 4; i++)
                #pragma unroll
                for (int c = 0; c < 4; c++)
                    acc[i][c] += a[i] * b[c];
        }
        __syncthreads();
    }
    float scale = (j == 0 || j == 7) ? SCALING : 1.0f;
    #pragma unroll
    for (int i = 0; i < 4; i++) {
        int row = row0 + ty * 4 + i;
        int s = row >> 2, b = row & 3;
        #pragma unroll
        for (int c = 0; c < 4; c++) {
            int col = col0 + tx * 4 + c;
            int eo = col - j * 256;
            float val = (acc[i][c] + bias[col]) * scale;
            g_proj[j][b * 8 + (eo >> 5)][s][eo & 31] = val;
        }
    }
}

// ---------------------------------------------------------------------------
// K tile stage: 256 cols x 32 d -> KT[col*33 + d]  (coalesced, conflict-free)
// ---------------------------------------------------------------------------
__device__ __forceinline__ void stage_tile(float* __restrict__ KT,
                                           const float* __restrict__ Ksrc,
                                           int ct, int t)
{
    for (int u = t * 4; u < 8192; u += 1024) {
        int col = u >> 5, dd = u & 31;
        float4 kv = *(const float4*)(Ksrc + (size_t)(ct * 256 + col) * 32 + dd);
        KT[col * 33 + dd + 0] = kv.x;
        KT[col * 33 + dd + 1] = kv.y;
        KT[col * 33 + dd + 2] = kv.z;
        KT[col * 33 + dd + 3] = kv.w;
    }
}

// 8-row x 1-col logit micro-tile, scalar FFMA.  Qt layout: Qt[d*8 + i].
__device__ __forceinline__ void logit_mac8(const float* __restrict__ KT,
                                           const float* __restrict__ Qt,
                                           int t, float acc[8])
{
    const float* kp = KT + t * 33;
    #pragma unroll
    for (int d = 0; d < 32; d++) {
        float kv = kp[d];
        const float4* qp = (const float4*)(Qt + d * 8);
        float4 q0 = qp[0], q1 = qp[1];
        acc[0] += q0.x * kv; acc[1] += q0.y * kv;
        acc[2] += q0.z * kv; acc[3] += q0.w * kv;
        acc[4] += q1.x * kv; acc[5] += q1.y * kv;
        acc[6] += q1.z * kv; acc[7] += q1.w * kv;
    }
}

// ---------------------------------------------------------------------------
// Kernel F1: per (bh, 8 rows): left/right logits -> softmax -> scans -> mask
// dyn smem floats: Ls[8192] Rs[8192] KT[8448] QtL[256] QtR[256] = 101376 B
// 2 CTAs/SM.
// ---------------------------------------------------------------------------
__global__ void __launch_bounds__(256, 2) f1_kernel()
{
    extern __shared__ float sm[];
    float* Ls  = sm;                 // 8192
    float* Rs  = sm + 8192;          // 8192
    float* KT  = sm + 16384;         // 8448
    float* QtL = sm + 24832;         // 256
    float* QtR = sm + 25088;         // 256
    int t = threadIdx.x, lane = t & 31, w = t >> 5;
    int rt = blockIdx.x, bh = blockIdx.y;
    int row0 = rt * 8;

    // stage both Q tiles once: t = d*8 + i
    {
        int d = t >> 3, i = t & 7;
        QtL[t] = g_proj[3][bh][row0 + i][d];
        QtR[t] = g_proj[5][bh][row0 + i][d];
    }

    #pragma unroll 1
    for (int m = 0; m < 2; m++) {
        const float* Ksrc = &g_proj[m == 0 ? 4 : 6][bh][0][0];
        const float* Qt = (m == 0) ? QtL : QtR;
        float* Obuf = (m == 0) ? Ls : Rs;
        #pragma unroll 1
        for (int ct = 0; ct < 4; ct++) {
            __syncthreads();                 // prev mac done with KT (and Qt visible)
            stage_tile(KT, Ksrc, ct, t);
            __syncthreads();
            float acc[8];
            #pragma unroll
            for (int i = 0; i < 8; i++) acc[i] = 0.f;
            logit_mac8(KT, Qt, t, acc);
            #pragma unroll
            for (int i = 0; i < 8; i++) Obuf[i * 1024 + ct * 256 + t] = acc[i];
        }
    }
    __syncthreads();

    // softmax: warp w owns row w of both L and R (interleaved for ILP)
    float* Lrow = Ls + w * 1024;
    float* Rrow = Rs + w * 1024;
    warp_softmax_row2(Lrow, Rrow, lane);

    // 2-level prefix/suffix -> mask (warp-local row)
    // P2[q][lane] = sum_{q'<=q} p[q'][lane];  S2 via s = B - p + v reversed.
    float sL[32], sR[32];
    float runPL = 0.f, runPR = 0.f;
    #pragma unroll
    for (int q = 0; q < 32; q++) {
        float vL = Lrow[q * 32 + lane];
        float vR = Rrow[q * 32 + lane];
        float pL = vL, pR = vR;
        warp_iscan2(pL, pR, lane);
        float BL = __shfl_sync(0xffffffffu, pL, 31);
        float BR = __shfl_sync(0xffffffffu, pR, 31);
        runPL += pL;                      // per-lane accumulation
        runPR += pR;
        Lrow[q * 32 + lane] = runPL;      // P2(L)
        Rrow[q * 32 + lane] = runPR;      // P2(R)
        sL[q] = BL - pL + vL;
        sR[q] = BR - pR + vR;
    }
    float* mout = &g_mask[bh][(size_t)(row0 + w) * 1024];
    float runSL = 0.f, runSR = 0.f;
    #pragma unroll
    for (int q = 31; q >= 0; q--) {
        runSL += sL[q];                   // S2(L)[q]
        runSR += sR[q];                   // S2(R)[q]
        mout[q * 32 + lane] = Lrow[q * 32 + lane] * runSR
                            + runSL * Rrow[q * 32 + lane];
    }
}

// ---------------------------------------------------------------------------
// Kernel F2: per (bh, 8 rows): global/local logits + mask combine -> softmax
// -> AV.  dyn smem floats: Cs[8192] KT[8448] Qt[256] = 67584 B.  3 CTAs/SM.
// AV: V direct from gmem (coalesced), partials reduced via smem (Ps = KT).
// ---------------------------------------------------------------------------
__global__ void __launch_bounds__(256, 3) f2_kernel()
{
    extern __shared__ float sm[];
    float* Cs = sm;                  // 8192
    float* KT = sm + 8192;           // 8448
    float* Qt = sm + 16640;          // 256
    float* Ps = KT;                  // AV partials overlay (2048 <= 8448)
    int t = threadIdx.x, lane = t & 31, w = t >> 5;
    int rt = blockIdx.x, bh = blockIdx.y;
    int row0 = rt * 8;

    #pragma unroll 1
    for (int m = 0; m < 2; m++) {
        const float* Qsrc = &g_proj[m == 0 ? 0 : 7][bh][0][0];
        const float* Ksrc = &g_proj[m == 0 ? 1 : 8][bh][0][0];
        __syncthreads();                 // prior phase done with Qt
        {
            int d = t >> 3, i = t & 7;
            Qt[t] = Qsrc[(row0 + i) * 32 + d];
        }
        #pragma unroll 1
        for (int ct = 0; ct < 4; ct++) {
            __syncthreads();             // prev mac done with KT; Qt visible
            stage_tile(KT, Ksrc, ct, t);
            __syncthreads();
            float acc[8];
            #pragma unroll
            for (int i = 0; i < 8; i++) acc[i] = 0.f;
            logit_mac8(KT, Qt, t, acc);
            if (m == 0) {
                #pragma unroll
                for (int i = 0; i < 8; i++) Cs[i * 1024 + ct * 256 + t] = acc[i];
            } else {
                const float* mrow = &g_mask[bh][(size_t)row0 * 1024 + ct * 256 + t];
                #pragma unroll
                for (int i = 0; i < 8; i++) {
                    int idx = i * 1024 + ct * 256 + t;
                    Cs[idx] = 0.1f * Cs[idx] + acc[i] * mrow[i * 1024];
                }
            }
        }
    }
    __syncthreads();

    // softmax attn weights: warp w owns row w
    warp_softmax_row(Cs + w * 1024, lane);
    __syncthreads();                     // all rows normalized before AV

    // ---- AV: thread (d=lane, jp=w) owns j-slice [128w, 128w+128) ----------
    const float* Vsrc = &g_proj[2][bh][0][0];
    int d = lane, jp = w;
    float acc[8];
    #pragma unroll
    for (int i = 0; i < 8; i++) acc[i] = 0.f;
    int base = jp * 128;
    #pragma unroll 4
    for (int jj = 0; jj < 128; jj += 4) {
        int j = base + jj;
        float v0 = Vsrc[(size_t)(j + 0) * 32 + d];
        float v1 = Vsrc[(size_t)(j + 1) * 32 + d];
        float v2 = Vsrc[(size_t)(j + 2) * 32 + d];
        float v3 = Vsrc[(size_t)(j + 3) * 32 + d];
        #pragma unroll
        for (int i = 0; i < 8; i++) {
            float4 c = *(const float4*)(Cs + i * 1024 + j);
            acc[i] += c.x * v0 + c.y * v1 + c.z * v2 + c.w * v3;
        }
    }
    #pragma unroll
    for (int i = 0; i < 8; i++) Ps[jp * 256 + i * 32 + d] = acc[i];
    __syncthreads();
    // reduce over jp: thread t -> output (row = w, dim = lane)
    float s = 0.f;
    #pragma unroll
    for (int p = 0; p < 8; p++) s += Ps[p * 256 + w * 32 + lane];
    int b = bh >> 3, h = bh & 7;
    g_attn_pre[((row0 + w) * 4 + b) * 256 + h * 32 + lane] = s;
}

// ---------------------------------------------------------------------------
// Kernel 4: out-projection.  out[4096 x 256] = attn_pre @ out_w^T + out_b
// ---------------------------------------------------------------------------
__global__ void __launch_bounds__(256) outproj_kernel(
        const float* __restrict__ W, const float* __restrict__ bias,
        float* __restrict__ out)
{
    __shared__ float As[16][68];
    __shared__ float Bs[16][68];
    int ct = blockIdx.x;  // 4
    int rt = blockIdx.y;  // 64
    int t = threadIdx.x;
    int tx = t & 15, ty = t >> 4;
    int row0 = rt * 64, col0 = ct * 64;
    float acc[4][4] = {};
    for (int kt = 0; kt < 256; kt += 16) {
        #pragma unroll
        for (int l = 0; l < 4; l++) {
            int u = t + l * 256;
            int kk = u & 15, m = u >> 4;
            As[kk][m] = g_attn_pre[(row0 + m) * 256 + kt + kk];
            Bs[kk][m] = W[(col0 + m) * 256 + kt + kk];
        }
        __syncthreads();
        #pragma unroll
        for (int kk = 0; kk < 16; kk++) {
            float4 av = *(const float4*)(&As[kk][ty * 4]);
            float4 bv = *(const float4*)(&Bs[kk][tx * 4]);
            float a[4] = {av.x, av.y, av.z, av.w};
            float b[4] = {bv.x, bv.y, bv.z, bv.w};
            #pragma unroll
            for (int i = 0; i < 4; i++)
                #pragma unroll
                for (int c = 0; c < 4; c++)
                    acc[i][c] += a[i] * b[c];
        }
        __syncthreads();
    }
    #pragma unroll
    for (int i = 0; i < 4; i++) {
        int row = row0 + ty * 4 + i;
        #pragma unroll
        for (int c = 0; c < 4; c++) {
            int col = col0 + tx * 4 + c;
            out[row * 256 + col] = acc[i][c] + bias[col];
        }
    }
}

// ---------------------------------------------------------------------------
// Kernel 5: consistent_mask = sum over bh of g_mask
// ---------------------------------------------------------------------------
__global__ void __launch_bounds__(256) mask_reduce_kernel(float* __restrict__ out)
{
    int idx = blockIdx.x * 256 + threadIdx.x;
    float s = 0.f;
    #pragma unroll
    for (int bh = 0; bh < 32; bh++) s += g_mask[bh][idx];
    out[idx] = s;
}

// ---------------------------------------------------------------------------
extern "C" void kernel_launch(void* const* d_in, const int* in_sizes, int n_in,
                              void* d_out, int out_size)
{
    const float* q   = (const float*)d_in[0];
    const float* k   = (const float*)d_in[1];
    const float* v   = (const float*)d_in[2];
    const float* ipw = (const float*)d_in[3];
    const float* ipb = (const float*)d_in[4];
    const float* ow  = (const float*)d_in[5];
    const float* ob  = (const float*)d_in[6];
    float* out = (float*)d_out;

    cudaFuncSetAttribute(f1_kernel, cudaFuncAttributeMaxDynamicSharedMemorySize, 101376);
    cudaFuncSetAttribute(f2_kernel, cudaFuncAttributeMaxDynamicSharedMemorySize, 67584);

    proj_kernel<<<dim3(36, 64), 256>>>(q, k, v, ipw, ipb);
    f1_kernel<<<dim3(128, 32), 256, 101376>>>();
    f2_kernel<<<dim3(128, 32), 256, 67584>>>();
    outproj_kernel<<<dim3(4, 64), 256>>>(ow, ob, out);
    mask_reduce_kernel<<<4096, 256>>>(out + 1048576);
}

// round 7
// speedup vs baseline: 1.6031x; 1.3098x over previous
#include <cuda_runtime.h>
#include <cuda_bf16.h>

#define SCALING 0.17677669529663687f

// ---------------------------------------------------------------------------
// Scratch (static device globals — allowed; no runtime allocation)
// ---------------------------------------------------------------------------
__device__ __nv_bfloat16 g_projh[9][32][1024][32];  // 18.9 MB  bf16 hi planes
__device__ __nv_bfloat16 g_projl[9][32][1024][32];  // 18.9 MB  bf16 lo planes
__device__ float g_v[32][1024][32];                 // 4.2 MB   V fp32 (AV)
__device__ float g_mask[32][1024 * 1024];           // 134 MB   local_mask
__device__ float g_attn_pre[4096 * 256];            // 4 MB     pre-out-proj

// ---------------------------------------------------------------------------
// mma.sync m16n8k16 bf16 (HMMA), D/C fp32
// A row-major 16x16, B col-major 16x8, D 16x8
// ---------------------------------------------------------------------------
__device__ __forceinline__ void mma_bf16(
    float& d0, float& d1, float& d2, float& d3,
    unsigned a0, unsigned a1, unsigned a2, unsigned a3,
    unsigned b0, unsigned b1)
{
    asm volatile(
        "mma.sync.aligned.m16n8k16.row.col.f32.bf16.bf16.f32 "
        "{%0,%1,%2,%3}, {%4,%5,%6,%7}, {%8,%9}, {%0,%1,%2,%3};\n"
        : "+f"(d0), "+f"(d1), "+f"(d2), "+f"(d3)
        : "r"(a0), "r"(a1), "r"(a2), "r"(a3), "r"(b0), "r"(b1));
}
__device__ __forceinline__ unsigned ldu32(const __nv_bfloat16* p) {
    return *(const unsigned*)p;
}

// ---------------------------------------------------------------------------
// warp helpers (R6-proven)
// ---------------------------------------------------------------------------
__device__ __forceinline__ void warp_iscan2(float& a, float& b, int lane) {
    #pragma unroll
    for (int o = 1; o < 32; o <<= 1) {
        float ua = __shfl_up_sync(0xffffffffu, a, o);
        float ub = __shfl_up_sync(0xffffffffu, b, o);
        if (lane >= o) { a += ua; b += ub; }
    }
}
__device__ __forceinline__ void warp_softmax_row2(float* r0, float* r1, int lane) {
    float m0 = -1e30f, m1 = -1e30f;
    #pragma unroll
    for (int q = 0; q < 32; q++) {
        m0 = fmaxf(m0, r0[q * 32 + lane]);
        m1 = fmaxf(m1, r1[q * 32 + lane]);
    }
    #pragma unroll
    for (int o = 16; o; o >>= 1) {
        m0 = fmaxf(m0, __shfl_xor_sync(0xffffffffu, m0, o));
        m1 = fmaxf(m1, __shfl_xor_sync(0xffffffffu, m1, o));
    }
    float s0 = 0.f, s1 = 0.f;
    #pragma unroll
    for (int q = 0; q < 32; q++) {
        float e0 = __expf(r0[q * 32 + lane] - m0);
        float e1 = __expf(r1[q * 32 + lane] - m1);
        r0[q * 32 + lane] = e0;
        r1[q * 32 + lane] = e1;
        s0 += e0; s1 += e1;
    }
    #pragma unroll
    for (int o = 16; o; o >>= 1) {
        s0 += __shfl_xor_sync(0xffffffffu, s0, o);
        s1 += __shfl_xor_sync(0xffffffffu, s1, o);
    }
    float i0 = 1.0f / s0, i1 = 1.0f / s1;
    #pragma unroll
    for (int q = 0; q < 32; q++) {
        r0[q * 32 + lane] *= i0;
        r1[q * 32 + lane] *= i1;
    }
}

// ---------------------------------------------------------------------------
// Kernel 1: packed in-projection (scalar FFMA) + split-bf16 emission
// ---------------------------------------------------------------------------
__global__ void __launch_bounds__(256) proj_kernel(
        const float* __restrict__ xq, const float* __restrict__ xk,
        const float* __restrict__ xv, const float* __restrict__ W,
        const float* __restrict__ bias)
{
    __shared__ float As[16][68];
    __shared__ float Bs[16][68];
    int ct = blockIdx.x;                 // 36 column tiles of 64
    int rt = blockIdx.y;                 // 64 row tiles of 64
    int j = ct >> 2;
    const float* X = (j == 2) ? xv
                   : ((j == 1 || j == 4 || j == 6 || j == 8) ? xk : xq);
    int t = threadIdx.x;
    int tx = t & 15, ty = t >> 4;
    int row0 = rt * 64, col0 = ct * 64;
    float acc[4][4] = {};
    for (int kt = 0; kt < 256; kt += 16) {
        #pragma unroll
        for (int l = 0; l < 4; l++) {
            int u = t + l * 256;
            int kk = u & 15, m = u >> 4;
            As[kk][m] = X[(row0 + m) * 256 + kt + kk];
            Bs[kk][m] = W[(col0 + m) * 256 + kt + kk];
        }
        __syncthreads();
        #pragma unroll
        for (int kk = 0; kk < 16; kk++) {
            float4 av = *(const float4*)(&As[kk][ty * 4]);
            float4 bv = *(const float4*)(&Bs[kk][tx * 4]);
            float a[4] = {av.x, av.y, av.z, av.w};
            float b[4] = {bv.x, bv.y, bv.z, bv.w};
            #pragma unroll
            for (int i = 0; i < 4; i++)
                #pragma unroll
                for (int c = 0; c < 4; c++)
                    acc[i][c] += a[i] * b[c];
        }
        __syncthreads();
    }
    float scale = (j == 0 || j == 7) ? SCALING : 1.0f;
    #pragma unroll
    for (int i = 0; i < 4; i++) {
        int row = row0 + ty * 4 + i;
        int s = row >> 2, b = row & 3;
        #pragma unroll
        for (int c = 0; c < 4; c++) {
            int col = col0 + tx * 4 + c;
            int eo = col - j * 256;
            float val = (acc[i][c] + bias[col]) * scale;
            int bhp = b * 8 + (eo >> 5), dd = eo & 31;
            __nv_bfloat16 h = __float2bfloat16(val);
            __nv_bfloat16 lo = __float2bfloat16(val - __bfloat162float(h));
            g_projh[j][bhp][s][dd] = h;
            g_projl[j][bhp][s][dd] = lo;
            if (j == 2) g_v[bhp][s][dd] = val;
        }
    }
}

// ---------------------------------------------------------------------------
// Kernel F1: per (bh, 8 rows): left/right logits (split-bf16 HMMA) ->
// softmax -> scans -> mask.  dyn smem: Ls[8192] Rs[8192] = 65536 B, 2 CTAs/SM
// ---------------------------------------------------------------------------
__global__ void __launch_bounds__(256, 2) f1_kernel()
{
    extern __shared__ float sm[];
    float* Ls = sm;
    float* Rs = sm + 8192;
    int t = threadIdx.x, lane = t & 31, w = t >> 5;
    int rt = blockIdx.x, bh = blockIdx.y;
    int row0 = rt * 8;
    int n = lane >> 2;            // 0..7: q-row within tile / A-row group
    int kq = (lane & 3) * 2;      // 0,2,4,6

    // B-frags: [mtx][hi/lo][kstep][reg]
    unsigned B[2][2][2][2];
    {
        const __nv_bfloat16* qh3 = &g_projh[3][bh][row0 + n][0];
        const __nv_bfloat16* ql3 = &g_projl[3][bh][row0 + n][0];
        const __nv_bfloat16* qh5 = &g_projh[5][bh][row0 + n][0];
        const __nv_bfloat16* ql5 = &g_projl[5][bh][row0 + n][0];
        B[0][0][0][0] = ldu32(qh3 + kq);      B[0][0][0][1] = ldu32(qh3 + kq + 8);
        B[0][0][1][0] = ldu32(qh3 + kq + 16); B[0][0][1][1] = ldu32(qh3 + kq + 24);
        B[0][1][0][0] = ldu32(ql3 + kq);      B[0][1][0][1] = ldu32(ql3 + kq + 8);
        B[0][1][1][0] = ldu32(ql3 + kq + 16); B[0][1][1][1] = ldu32(ql3 + kq + 24);
        B[1][0][0][0] = ldu32(qh5 + kq);      B[1][0][0][1] = ldu32(qh5 + kq + 8);
        B[1][0][1][0] = ldu32(qh5 + kq + 16); B[1][0][1][1] = ldu32(qh5 + kq + 24);
        B[1][1][0][0] = ldu32(ql5 + kq);      B[1][1][0][1] = ldu32(ql5 + kq + 8);
        B[1][1][1][0] = ldu32(ql5 + kq + 16); B[1][1][1][1] = ldu32(ql5 + kq + 24);
    }

    #pragma unroll 1
    for (int m = 0; m < 2; m++) {
        const __nv_bfloat16* Kh = &g_projh[m ? 6 : 4][bh][0][0];
        const __nv_bfloat16* Kl = &g_projl[m ? 6 : 4][bh][0][0];
        float* Obuf = m ? Rs : Ls;
        #pragma unroll 1
        for (int j = 0; j < 8; j++) {
            int col0 = (j * 8 + w) * 16;
            float d0 = 0.f, d1 = 0.f, d2 = 0.f, d3 = 0.f;
            #pragma unroll
            for (int ks = 0; ks < 2; ks++) {
                int off = ks * 16 + kq;
                const __nv_bfloat16* pa0 = Kh + (col0 + n) * 32 + off;
                const __nv_bfloat16* pa1 = Kh + (col0 + n + 8) * 32 + off;
                const __nv_bfloat16* pl0 = Kl + (col0 + n) * 32 + off;
                const __nv_bfloat16* pl1 = Kl + (col0 + n + 8) * 32 + off;
                unsigned ah0 = ldu32(pa0),     ah1 = ldu32(pa1);
                unsigned ah2 = ldu32(pa0 + 8), ah3 = ldu32(pa1 + 8);
                unsigned al0 = ldu32(pl0),     al1 = ldu32(pl1);
                unsigned al2 = ldu32(pl0 + 8), al3 = ldu32(pl1 + 8);
                mma_bf16(d0, d1, d2, d3, ah0, ah1, ah2, ah3,
                         B[m][0][ks][0], B[m][0][ks][1]);   // hi*hi
                mma_bf16(d0, d1, d2, d3, al0, al1, al2, al3,
                         B[m][0][ks][0], B[m][0][ks][1]);   // lo*hi
                mma_bf16(d0, d1, d2, d3, ah0, ah1, ah2, ah3,
                         B[m][1][ks][0], B[m][1][ks][1]);   // hi*lo
            }
            int c = col0 + n;
            Obuf[kq * 1024 + c]           = d0;
            Obuf[(kq + 1) * 1024 + c]     = d1;
            Obuf[kq * 1024 + c + 8]       = d2;
            Obuf[(kq + 1) * 1024 + c + 8] = d3;
        }
    }
    __syncthreads();

    // ---- softmax + 2-level prefix/suffix -> mask (R6-proven, warp row w) --
    float* Lrow = Ls + w * 1024;
    float* Rrow = Rs + w * 1024;
    warp_softmax_row2(Lrow, Rrow, lane);

    float sL[32], sR[32];
    float runPL = 0.f, runPR = 0.f;
    #pragma unroll
    for (int q = 0; q < 32; q++) {
        float vL = Lrow[q * 32 + lane];
        float vR = Rrow[q * 32 + lane];
        float pL = vL, pR = vR;
        warp_iscan2(pL, pR, lane);
        float BL = __shfl_sync(0xffffffffu, pL, 31);
        float BR = __shfl_sync(0xffffffffu, pR, 31);
        runPL += pL;
        runPR += pR;
        Lrow[q * 32 + lane] = runPL;      // P2(L)
        Rrow[q * 32 + lane] = runPR;      // P2(R)
        sL[q] = BL - pL + vL;
        sR[q] = BR - pR + vR;
    }
    float* mout = &g_mask[bh][(size_t)(row0 + w) * 1024];
    float runSL = 0.f, runSR = 0.f;
    #pragma unroll
    for (int q = 31; q >= 0; q--) {
        runSL += sL[q];
        runSR += sR[q];
        mout[q * 32 + lane] = Lrow[q * 32 + lane] * runSR
                            + runSL * Rrow[q * 32 + lane];
    }
}

// ---------------------------------------------------------------------------
// Kernel F2: per (bh, 16 rows): global+local logits (HMMA) + mask combine ->
// softmax -> AV (SIMT fp32).  dyn smem: Cs[16384] Ps[4096] = 81920 B, 2 CTAs/SM
// ---------------------------------------------------------------------------
__global__ void __launch_bounds__(256, 2) f2_kernel()
{
    extern __shared__ float sm[];
    float* Cs = sm;                  // 16 x 1024
    float* Ps = sm + 16384;          // 8 x 16 x 32 AV partials
    int t = threadIdx.x, lane = t & 31, w = t >> 5;
    int rt = blockIdx.x, bh = blockIdx.y;
    int row0 = rt * 16;
    int n = lane >> 2, kq = (lane & 3) * 2;

    // B-frags: [mtx][rowhalf][hi/lo][kstep][reg]
    unsigned B[2][2][2][2][2];
    #pragma unroll
    for (int mtx = 0; mtx < 2; mtx++) {
        int slice = mtx ? 7 : 0;
        #pragma unroll
        for (int rh = 0; rh < 2; rh++) {
            const __nv_bfloat16* qh = &g_projh[slice][bh][row0 + rh * 8 + n][0];
            const __nv_bfloat16* ql = &g_projl[slice][bh][row0 + rh * 8 + n][0];
            B[mtx][rh][0][0][0] = ldu32(qh + kq);      B[mtx][rh][0][0][1] = ldu32(qh + kq + 8);
            B[mtx][rh][0][1][0] = ldu32(qh + kq + 16); B[mtx][rh][0][1][1] = ldu32(qh + kq + 24);
            B[mtx][rh][1][0][0] = ldu32(ql + kq);      B[mtx][rh][1][0][1] = ldu32(ql + kq + 8);
            B[mtx][rh][1][1][0] = ldu32(ql + kq + 16); B[mtx][rh][1][1][1] = ldu32(ql + kq + 24);
        }
    }

    const __nv_bfloat16* K1h = &g_projh[1][bh][0][0];
    const __nv_bfloat16* K1l = &g_projl[1][bh][0][0];
    const __nv_bfloat16* K8h = &g_projh[8][bh][0][0];
    const __nv_bfloat16* K8l = &g_projl[8][bh][0][0];

    #pragma unroll 1
    for (int j = 0; j < 8; j++) {
        int col0 = (j * 8 + w) * 16;
        float g[8] = {}, lc[8] = {};
        // global logits: Q0 . K1
        #pragma unroll
        for (int ks = 0; ks < 2; ks++) {
            int off = ks * 16 + kq;
            const __nv_bfloat16* pa0 = K1h + (col0 + n) * 32 + off;
            const __nv_bfloat16* pa1 = K1h + (col0 + n + 8) * 32 + off;
            const __nv_bfloat16* pl0 = K1l + (col0 + n) * 32 + off;
            const __nv_bfloat16* pl1 = K1l + (col0 + n + 8) * 32 + off;
            unsigned ah0 = ldu32(pa0),     ah1 = ldu32(pa1);
            unsigned ah2 = ldu32(pa0 + 8), ah3 = ldu32(pa1 + 8);
            unsigned al0 = ldu32(pl0),     al1 = ldu32(pl1);
            unsigned al2 = ldu32(pl0 + 8), al3 = ldu32(pl1 + 8);
            #pragma unroll
            for (int rh = 0; rh < 2; rh++) {
                mma_bf16(g[rh*4+0], g[rh*4+1], g[rh*4+2], g[rh*4+3],
                         ah0, ah1, ah2, ah3, B[0][rh][0][ks][0], B[0][rh][0][ks][1]);
                mma_bf16(g[rh*4+0], g[rh*4+1], g[rh*4+2], g[rh*4+3],
                         al0, al1, al2, al3, B[0][rh][0][ks][0], B[0][rh][0][ks][1]);
                mma_bf16(g[rh*4+0], g[rh*4+1], g[rh*4+2], g[rh*4+3],
                         ah0, ah1, ah2, ah3, B[0][rh][1][ks][0], B[0][rh][1][ks][1]);
            }
        }
        // local logits: Q7 . K8
        #pragma unroll
        for (int ks = 0; ks < 2; ks++) {
            int off = ks * 16 + kq;
            const __nv_bfloat16* pa0 = K8h + (col0 + n) * 32 + off;
            const __nv_bfloat16* pa1 = K8h + (col0 + n + 8) * 32 + off;
            const __nv_bfloat16* pl0 = K8l + (col0 + n) * 32 + off;
            const __nv_bfloat16* pl1 = K8l + (col0 + n + 8) * 32 + off;
            unsigned ah0 = ldu32(pa0),     ah1 = ldu32(pa1);
            unsigned ah2 = ldu32(pa0 + 8), ah3 = ldu32(pa1 + 8);
            unsigned al0 = ldu32(pl0),     al1 = ldu32(pl1);
            unsigned al2 = ldu32(pl0 + 8), al3 = ldu32(pl1 + 8);
            #pragma unroll
            for (int rh = 0; rh < 2; rh++) {
                mma_bf16(lc[rh*4+0], lc[rh*4+1], lc[rh*4+2], lc[rh*4+3],
                         ah0, ah1, ah2, ah3, B[1][rh][0][ks][0], B[1][rh][0][ks][1]);
                mma_bf16(lc[rh*4+0], lc[rh*4+1], lc[rh*4+2], lc[rh*4+3],
                         al0, al1, al2, al3, B[1][rh][0][ks][0], B[1][rh][0][ks][1]);
                mma_bf16(lc[rh*4+0], lc[rh*4+1], lc[rh*4+2], lc[rh*4+3],
                         ah0, ah1, ah2, ah3, B[1][rh][1][ks][0], B[1][rh][1][ks][1]);
            }
        }
        // combine with mask and store
        int c = col0 + n;
        #pragma unroll
        for (int rh = 0; rh < 2; rh++) {
            int q = rh * 8 + kq;
            const float* mrow = &g_mask[bh][(size_t)(row0 + q) * 1024];
            float m0 = mrow[c], m1 = mrow[1024 + c];
            float m2 = mrow[c + 8], m3 = mrow[1024 + c + 8];
            Cs[q * 1024 + c]           = 0.1f * g[rh*4+0] + lc[rh*4+0] * m0;
            Cs[(q + 1) * 1024 + c]     = 0.1f * g[rh*4+1] + lc[rh*4+1] * m1;
            Cs[q * 1024 + c + 8]       = 0.1f * g[rh*4+2] + lc[rh*4+2] * m2;
            Cs[(q + 1) * 1024 + c + 8] = 0.1f * g[rh*4+3] + lc[rh*4+3] * m3;
        }
    }
    __syncthreads();

    // softmax: warp w owns rows w and w+8
    warp_softmax_row2(Cs + w * 1024, Cs + (w + 8) * 1024, lane);
    __syncthreads();

    // ---- AV: thread (d=lane, jp=w) owns j-slice [128w, 128w+128) ----------
    const float* Vsrc = &g_v[bh][0][0];
    int d = lane, jp = w;
    float acc[16];
    #pragma unroll
    for (int i = 0; i < 16; i++) acc[i] = 0.f;
    int base = jp * 128;
    #pragma unroll 2
    for (int jj = 0; jj < 128; jj += 4) {
        int j = base + jj;
        float v0 = Vsrc[(size_t)(j + 0) * 32 + d];
        float v1 = Vsrc[(size_t)(j + 1) * 32 + d];
        float v2 = Vsrc[(size_t)(j + 2) * 32 + d];
        float v3 = Vsrc[(size_t)(j + 3) * 32 + d];
        #pragma unroll
        for (int i = 0; i < 16; i++) {
            float4 c4 = *(const float4*)(Cs + i * 1024 + j);
            acc[i] += c4.x * v0 + c4.y * v1 + c4.z * v2 + c4.w * v3;
        }
    }
    #pragma unroll
    for (int i = 0; i < 16; i++) Ps[jp * 512 + i * 32 + d] = acc[i];
    __syncthreads();
    // reduce over jp: thread -> rows (w, w+8), dim lane
    float s0 = 0.f, s1 = 0.f;
    #pragma unroll
    for (int p = 0; p < 8; p++) {
        s0 += Ps[p * 512 + w * 32 + lane];
        s1 += Ps[p * 512 + (w + 8) * 32 + lane];
    }
    int b = bh >> 3, h = bh & 7;
    g_attn_pre[((row0 + w) * 4 + b) * 256 + h * 32 + lane] = s0;
    g_attn_pre[((row0 + w + 8) * 4 + b) * 256 + h * 32 + lane] = s1;
}

// ---------------------------------------------------------------------------
// Kernel 4: out-projection.  out[4096 x 256] = attn_pre @ out_w^T + out_b
// ---------------------------------------------------------------------------
__global__ void __launch_bounds__(256) outproj_kernel(
        const float* __restrict__ W, const float* __restrict__ bias,
        float* __restrict__ out)
{
    __shared__ float As[16][68];
    __shared__ float Bs[16][68];
    int ct = blockIdx.x;  // 4
    int rt = blockIdx.y;  // 64
    int t = threadIdx.x;
    int tx = t & 15, ty = t >> 4;
    int row0 = rt * 64, col0 = ct * 64;
    float acc[4][4] = {};
    for (int kt = 0; kt < 256; kt += 16) {
        #pragma unroll
        for (int l = 0; l < 4; l++) {
            int u = t + l * 256;
            int kk = u & 15, m = u >> 4;
            As[kk][m] = g_attn_pre[(row0 + m) * 256 + kt + kk];
            Bs[kk][m] = W[(col0 + m) * 256 + kt + kk];
        }
        __syncthreads();
        #pragma unroll
        for (int kk = 0; kk < 16; kk++) {
            float4 av = *(const float4*)(&As[kk][ty * 4]);
            float4 bv = *(const float4*)(&Bs[kk][tx * 4]);
            float a[4] = {av.x, av.y, av.z, av.w};
            float b[4] = {bv.x, bv.y, bv.z, bv.w};
            #pragma unroll
            for (int i = 0; i < 4; i++)
                #pragma unroll
                for (int c = 0; c < 4; c++)
                    acc[i][c] += a[i] * b[c];
        }
        __syncthreads();
    }
    #pragma unroll
    for (int i = 0; i < 4; i++) {
        int row = row0 + ty * 4 + i;
        #pragma unroll
        for (int c = 0; c < 4; c++) {
            int col = col0 + tx * 4 + c;
            out[row * 256 + col] = acc[i][c] + bias[col];
        }
    }
}

// ---------------------------------------------------------------------------
// Kernel 5: consistent_mask = sum over bh of g_mask
// ---------------------------------------------------------------------------
__global__ void __launch_bounds__(256) mask_reduce_kernel(float* __restrict__ out)
{
    int idx = blockIdx.x * 256 + threadIdx.x;
    float s = 0.f;
    #pragma unroll
    for (int bh = 0; bh < 32; bh++) s += g_mask[bh][idx];
    out[idx] = s;
}

// ---------------------------------------------------------------------------
extern "C" void kernel_launch(void* const* d_in, const int* in_sizes, int n_in,
                              void* d_out, int out_size)
{
    const float* q   = (const float*)d_in[0];
    const float* k   = (const float*)d_in[1];
    const float* v   = (const float*)d_in[2];
    const float* ipw = (const float*)d_in[3];
    const float* ipb = (const float*)d_in[4];
    const float* ow  = (const float*)d_in[5];
    const float* ob  = (const float*)d_in[6];
    float* out = (float*)d_out;

    cudaFuncSetAttribute(f1_kernel, cudaFuncAttributeMaxDynamicSharedMemorySize, 65536);
    cudaFuncSetAttribute(f2_kernel, cudaFuncAttributeMaxDynamicSharedMemorySize, 81920);

    proj_kernel<<<dim3(36, 64), 256>>>(q, k, v, ipw, ipb);
    f1_kernel<<<dim3(128, 32), 256, 65536>>>();
    f2_kernel<<<dim3(64, 32), 256, 81920>>>();
    outproj_kernel<<<dim3(4, 64), 256>>>(ow, ob, out);
    mask_reduce_kernel<<<4096, 256>>>(out + 1048576);
}